// round 1
// baseline (speedup 1.0000x reference)
#include <cuda_runtime.h>

#define D  64
#define NA 64
#define MAX_ITEM 100000
#define MAX_BZ   1024

// Scratch tables (allocation-free: __device__ globals)
__device__ float g_RuA[NA];
__device__ float g_RpA[NA];
__device__ float g_RnA[NA];
__device__ float g_P[MAX_BZ * NA];          // 256 KB
__device__ float g_Qd[(size_t)MAX_ITEM * NA]; // 25.6 MB, lives in L2 during main pass

// ---------------------------------------------------------------------------
// Kernel 0: relation @ A^T  (3 x 64 dots of 64)  — trivial
// ---------------------------------------------------------------------------
__global__ void relA_kernel(const float* __restrict__ rel,
                            const float* __restrict__ A) {
    int t = threadIdx.x;           // 0..191
    int r = t >> 6, a = t & 63;
    const float* rv = rel + r * D;
    const float* av = A + a * D;
    float s = 0.f;
#pragma unroll
    for (int d = 0; d < D; d++) s += rv[d] * av[d];
    if (r == 0)      g_RuA[a] = s;
    else if (r == 1) g_RpA[a] = s;
    else             g_RnA[a] = s;
}

// Shared helper: build At2[d*32 + a] = (A[a][d], A[a+32][d]) — conflict-free
// LDS.64 in the inner product loops.
__device__ __forceinline__ void fill_At2(float2* At2, const float* __restrict__ A) {
    for (int idx = threadIdx.x; idx < 64 * 64; idx += blockDim.x) {
        int a = idx >> 6, d = idx & 63;
        float v = A[a * 64 + d];
        float* base = (float*)&At2[d * 32 + (a & 31)];
        base[a >> 5] = v;   // x for a<32, y for a>=32
    }
}

// ---------------------------------------------------------------------------
// Kernel 1: P[b] = softmax(U[b]@A^T + RuA)   (one warp per row)
// ---------------------------------------------------------------------------
__global__ void p_kernel(const int* __restrict__ uidx,
                         const float* __restrict__ Uemb,
                         const float* __restrict__ A, int bz) {
    __shared__ float2 At2[64 * 32];
    __shared__ float  us[8][64];
    fill_At2(At2, A);
    int w = threadIdx.x >> 5, lane = threadIdx.x & 31;
    float ru0 = g_RuA[lane], ru1 = g_RuA[lane + 32];
    __syncthreads();
    int row = blockIdx.x * 8 + w;
    if (row >= bz) return;

    const float* U = Uemb + (size_t)uidx[row] * D;
    ((float2*)us[w])[lane] = ((const float2*)U)[lane];
    __syncwarp();

    float acc0 = 0.f, acc1 = 0.f;
#pragma unroll
    for (int d = 0; d < 64; d++) {
        float  u  = us[w][d];           // LDS broadcast
        float2 a2 = At2[d * 32 + lane]; // LDS.64 conflict-free
        acc0 += u * a2.x;
        acc1 += u * a2.y;
    }
    float l0 = acc0 + ru0, l1 = acc1 + ru1;
    float m = fmaxf(l0, l1);
#pragma unroll
    for (int o = 16; o; o >>= 1) m = fmaxf(m, __shfl_xor_sync(0xffffffffu, m, o));
    float e0 = __expf(l0 - m), e1 = __expf(l1 - m);
    float s = e0 + e1;
#pragma unroll
    for (int o = 16; o; o >>= 1) s += __shfl_xor_sync(0xffffffffu, s, o);
    float inv = __fdividef(1.f, s);
    g_P[row * NA + lane]      = e0 * inv;
    g_P[row * NA + lane + 32] = e1 * inv;
}

// ---------------------------------------------------------------------------
// Kernel 2: Qd[item] = softmax(I@A^T + RpA) - softmax(I@A^T + RnA)
// 8 warps/block, each warp processes 4 consecutive items at a time (2 iters)
// → 64 items/block.
// ---------------------------------------------------------------------------
__global__ void qd_kernel(const float* __restrict__ Iemb,
                          const float* __restrict__ A, int nitem) {
    __shared__ float2 At2[64 * 32];        // 16 KB
    __shared__ float  Ism[8][320];         // padded interleave per warp
    fill_At2(At2, A);
    int w = threadIdx.x >> 5, lane = threadIdx.x & 31;
    float rp0 = g_RpA[lane], rp1 = g_RpA[lane + 32];
    float rn0 = g_RnA[lane], rn1 = g_RnA[lane + 32];
    __syncthreads();

    int blockBase = blockIdx.x * 64;
#pragma unroll 1
    for (int it = 0; it < 2; it++) {
        int base4 = blockBase + w * 8 + it * 4;   // 4 consecutive items
        if (base4 >= nitem) break;                 // nitem % 4 == 0

        // Cooperative load: 4 consecutive rows = 256 contiguous floats.
        // float4 #f : j = f>>4 (item), q = f&15 (covers d = 4q..4q+3)
        const float4* g4 = (const float4*)(Iemb + (size_t)base4 * D);
        float4 v1 = g4[lane];
        float4 v2 = g4[lane + 32];
        __syncwarp();  // previous iteration's readers done
        {
            int f, j, q;
            f = lane;      j = f >> 4; q = f & 15;
#pragma unroll
            for (int k = 0; k < 4; k++)
                Ism[w][20 * q + 4 * k + j] = ((float*)&v1)[k];
            f = lane + 32; j = f >> 4; q = f & 15;
#pragma unroll
            for (int k = 0; k < 4; k++)
                Ism[w][20 * q + 4 * k + j] = ((float*)&v2)[k];
        }
        __syncwarp();

        float acc00 = 0.f, acc01 = 0.f, acc10 = 0.f, acc11 = 0.f;
        float acc20 = 0.f, acc21 = 0.f, acc30 = 0.f, acc31 = 0.f;
#pragma unroll
        for (int d = 0; d < 64; d++) {
            float2 a2 = At2[d * 32 + lane];                       // LDS.64
            float4 iv = *(const float4*)&Ism[w][d * 4 + (d >> 2) * 4]; // LDS.128 bcast
            acc00 += iv.x * a2.x; acc01 += iv.x * a2.y;
            acc10 += iv.y * a2.x; acc11 += iv.y * a2.y;
            acc20 += iv.z * a2.x; acc21 += iv.z * a2.y;
            acc30 += iv.w * a2.x; acc31 += iv.w * a2.y;
        }

        float L0s[4] = {acc00, acc10, acc20, acc30};
        float L1s[4] = {acc01, acc11, acc21, acc31};
#pragma unroll
        for (int j = 0; j < 4; j++) {
            float L0 = L0s[j], L1 = L1s[j];
            float lp0 = L0 + rp0, lp1 = L1 + rp1;
            float ln0 = L0 + rn0, ln1 = L1 + rn1;
            float mp = fmaxf(lp0, lp1), mn = fmaxf(ln0, ln1);
#pragma unroll
            for (int o = 16; o; o >>= 1) {
                mp = fmaxf(mp, __shfl_xor_sync(0xffffffffu, mp, o));
                mn = fmaxf(mn, __shfl_xor_sync(0xffffffffu, mn, o));
            }
            float ep0 = __expf(lp0 - mp), ep1 = __expf(lp1 - mp);
            float en0 = __expf(ln0 - mn), en1 = __expf(ln1 - mn);
            float sp = ep0 + ep1, sn = en0 + en1;
#pragma unroll
            for (int o = 16; o; o >>= 1) {
                sp += __shfl_xor_sync(0xffffffffu, sp, o);
                sn += __shfl_xor_sync(0xffffffffu, sn, o);
            }
            float ip = __fdividef(1.f, sp);
            float in_ = __fdividef(1.f, sn);
            float* orow = g_Qd + (size_t)(base4 + j) * NA;
            orow[lane]      = ep0 * ip - en0 * in_;
            orow[lane + 32] = ep1 * ip - en1 * in_;
        }
    }
}

// ---------------------------------------------------------------------------
// Kernel 3: ratings[b,n] = P[b] . Qd[item[b,n]] + bias[item]; softmax over n.
// One block per b. 8-lane groups gather one 256B row via 2 coalesced LDG.128.
// ---------------------------------------------------------------------------
__global__ void main_kernel(const int* __restrict__ iidx,
                            const float* __restrict__ bias,
                            float* __restrict__ out, int ns) {
    __shared__ float Ps[64];
    __shared__ float rat[1024];
    __shared__ float red[8];
    int b = blockIdx.x;
    int t = threadIdx.x;
    if (t < 16) ((float4*)Ps)[t] = ((const float4*)(g_P + b * 64))[t];
    __syncthreads();

    int w = t >> 5, lane = t & 31, g = lane >> 3, q = lane & 7;
    float4 p0 = ((float4*)Ps)[q];
    float4 p1 = ((float4*)Ps)[q + 8];
    const int* idxrow = iidx + (size_t)b * ns;

    for (int s0 = w * 4; s0 < ns; s0 += 32) {
        int s = s0 + g;
        float r = 0.f;
        int item = 0;
        if (s < ns) {
            item = idxrow[s];                                 // broadcast in group
            const float4* row = (const float4*)(g_Qd + (size_t)item * 64);
            float4 a = row[q];       // bytes [0,128)   -> 1 line/sample
            float4 c = row[q + 8];   // bytes [128,256) -> 1 line/sample
            r = a.x * p0.x + a.y * p0.y + a.z * p0.z + a.w * p0.w
              + c.x * p1.x + c.y * p1.y + c.z * p1.z + c.w * p1.w;
        }
        r += __shfl_xor_sync(0xffffffffu, r, 1);
        r += __shfl_xor_sync(0xffffffffu, r, 2);
        r += __shfl_xor_sync(0xffffffffu, r, 4);
        if (s < ns && q == 0) rat[s] = r + bias[item];
    }
    __syncthreads();

    // block softmax over rat[0..ns)
    float m = -1e30f;
    for (int s = t; s < ns; s += 256) m = fmaxf(m, rat[s]);
#pragma unroll
    for (int o = 16; o; o >>= 1) m = fmaxf(m, __shfl_xor_sync(0xffffffffu, m, o));
    if (lane == 0) red[w] = m;
    __syncthreads();
    if (t == 0) {
        float v = red[0];
#pragma unroll
        for (int i = 1; i < 8; i++) v = fmaxf(v, red[i]);
        red[0] = v;
    }
    __syncthreads();
    m = red[0];
    __syncthreads();   // protect red[] before sum phase reuses it

    float sum = 0.f;
    for (int s = t; s < ns; s += 256) {
        float e = __expf(rat[s] - m);
        rat[s] = e;
        sum += e;
    }
#pragma unroll
    for (int o = 16; o; o >>= 1) sum += __shfl_xor_sync(0xffffffffu, sum, o);
    if (lane == 0) red[w] = sum;
    __syncthreads();
    if (t == 0) {
        float v = red[0];
#pragma unroll
        for (int i = 1; i < 8; i++) v += red[i];
        red[0] = v;
    }
    __syncthreads();
    float inv = __fdividef(1.f, red[0]);
    float* orow = out + (size_t)b * ns;
    for (int s = t; s < ns; s += 256) orow[s] = rat[s] * inv;
}

// ---------------------------------------------------------------------------
// Launch
// ---------------------------------------------------------------------------
extern "C" void kernel_launch(void* const* d_in, const int* in_sizes, int n_in,
                              void* d_out, int out_size) {
    const int*   uidx = (const int*)d_in[0];
    const int*   iidx = (const int*)d_in[1];
    const float* Uemb = (const float*)d_in[2];
    const float* Iemb = (const float*)d_in[3];
    const float* A    = (const float*)d_in[4];
    const float* Rel  = (const float*)d_in[5];
    const float* bias = (const float*)d_in[6];
    float* out = (float*)d_out;

    int bz    = in_sizes[0];
    int ns    = in_sizes[1] / bz;
    int nitem = in_sizes[3] / D;

    relA_kernel<<<1, 192>>>(Rel, A);
    p_kernel<<<(bz + 7) / 8, 256>>>(uidx, Uemb, A, bz);
    qd_kernel<<<(nitem + 63) / 64, 256>>>(Iemb, A, nitem);
    main_kernel<<<bz, 256>>>(iidx, bias, out, ns);
}

// round 2
// speedup vs baseline: 1.2093x; 1.2093x over previous
#include <cuda_runtime.h>

#define D  64
#define NA 64
#define MAX_ITEM 100000
#define MAX_BZ   1024

// Scratch tables (allocation-free: __device__ globals)
__device__ float g_P[MAX_BZ * NA];            // 256 KB
__device__ float g_Qd[(size_t)MAX_ITEM * NA]; // 25.6 MB, L2-resident in main pass

// ---------------------------------------------------------------------------
// Shared helper: At2[d*32 + a] = (A[a][d], A[a+32][d]) — conflict-free LDS.64
// ---------------------------------------------------------------------------
__device__ __forceinline__ void fill_At2(float2* At2, const float* __restrict__ A) {
    for (int idx = threadIdx.x; idx < 64 * 64; idx += blockDim.x) {
        int a = idx >> 6, d = idx & 63;
        float v = A[a * 64 + d];
        float* base = (float*)&At2[d * 32 + (a & 31)];
        base[a >> 5] = v;   // x for a<32, y for a>=32
    }
}

// ---------------------------------------------------------------------------
// Kernel 1 (fused): blocks [0, QB) compute Qd table; blocks [QB, QB+PB) compute P.
// Each block computes its own relation@A^T projections (cheap, smem-resident A).
// ---------------------------------------------------------------------------
__global__ void __launch_bounds__(256) prep_kernel(
        const int* __restrict__ uidx,
        const float* __restrict__ Uemb,
        const float* __restrict__ Iemb,
        const float* __restrict__ A,
        const float* __restrict__ Rel,
        int bz, int nitem, int QB) {
    __shared__ float2 At2[64 * 32];      // 16 KB
    __shared__ float  sR[128];           // qd: RpA[64] | RnA[64] ; p: RuA[64]
    __shared__ float  Ism[8][320];       // qd: padded I-tile ; p: first 64 = user emb
    fill_At2(At2, A);
    __syncthreads();

    int t = threadIdx.x;
    int w = t >> 5, lane = t & 31;
    bool isQ = blockIdx.x < QB;

    // ---- per-block relation projections (read A from smem, Rel broadcast) ----
    if (isQ) {
        if (t < 128) {
            int rr = 1 + (t >> 6);       // 1 = Rip, 2 = Rin
            int a  = t & 63;
            const float* rv = Rel + rr * D;
            float s = 0.f;
#pragma unroll
            for (int d = 0; d < 64; d++) {
                float2 v = At2[d * 32 + (a & 31)];
                s += rv[d] * ((a >= 32) ? v.y : v.x);
            }
            sR[t] = s;                    // [0,64)=RpA, [64,128)=RnA
        }
    } else {
        if (t < 64) {
            int a = t;
            float s = 0.f;
#pragma unroll
            for (int d = 0; d < 64; d++) {
                float2 v = At2[d * 32 + (a & 31)];
                s += Rel[d] * ((a >= 32) ? v.y : v.x);
            }
            sR[t] = s;                    // RuA
        }
    }
    __syncthreads();

    if (isQ) {
        // ================= Qd blocks: 64 items/block =================
        float rp0 = sR[lane],      rp1 = sR[lane + 32];
        float rn0 = sR[64 + lane], rn1 = sR[96 + lane];
        int blockBase = blockIdx.x * 64;
#pragma unroll 1
        for (int it = 0; it < 2; it++) {
            int base4 = blockBase + w * 8 + it * 4;   // 4 consecutive items
            if (base4 >= nitem) break;                // nitem % 4 == 0

            // Cooperative load: 4 rows = 256 contiguous floats.
            const float4* g4 = (const float4*)(Iemb + (size_t)base4 * D);
            float4 v1 = g4[lane];
            float4 v2 = g4[lane + 32];
            __syncwarp();
            {
                int f, j, q;
                f = lane;      j = f >> 4; q = f & 15;
#pragma unroll
                for (int k = 0; k < 4; k++)
                    Ism[w][20 * q + 4 * k + j] = ((float*)&v1)[k];
                f = lane + 32; j = f >> 4; q = f & 15;
#pragma unroll
                for (int k = 0; k < 4; k++)
                    Ism[w][20 * q + 4 * k + j] = ((float*)&v2)[k];
            }
            __syncwarp();

            float acc00 = 0.f, acc01 = 0.f, acc10 = 0.f, acc11 = 0.f;
            float acc20 = 0.f, acc21 = 0.f, acc30 = 0.f, acc31 = 0.f;
#pragma unroll
            for (int d = 0; d < 64; d++) {
                float2 a2 = At2[d * 32 + lane];                            // LDS.64
                float4 iv = *(const float4*)&Ism[w][d * 4 + (d >> 2) * 4]; // LDS.128 bcast
                acc00 += iv.x * a2.x; acc01 += iv.x * a2.y;
                acc10 += iv.y * a2.x; acc11 += iv.y * a2.y;
                acc20 += iv.z * a2.x; acc21 += iv.z * a2.y;
                acc30 += iv.w * a2.x; acc31 += iv.w * a2.y;
            }

            float L0s[4] = {acc00, acc10, acc20, acc30};
            float L1s[4] = {acc01, acc11, acc21, acc31};
#pragma unroll
            for (int j = 0; j < 4; j++) {
                float L0 = L0s[j], L1 = L1s[j];
                // single shared max of the raw logits (valid shift for both softmaxes)
                float m = fmaxf(L0, L1);
#pragma unroll
                for (int o = 16; o; o >>= 1)
                    m = fmaxf(m, __shfl_xor_sync(0xffffffffu, m, o));
                float ep0 = __expf(L0 - m + rp0), ep1 = __expf(L1 - m + rp1);
                float en0 = __expf(L0 - m + rn0), en1 = __expf(L1 - m + rn1);
                float sp = ep0 + ep1, sn = en0 + en1;
#pragma unroll
                for (int o = 16; o; o >>= 1) {
                    sp += __shfl_xor_sync(0xffffffffu, sp, o);
                    sn += __shfl_xor_sync(0xffffffffu, sn, o);
                }
                float ipv = __fdividef(1.f, sp);
                float inv = __fdividef(1.f, sn);
                float* orow = g_Qd + (size_t)(base4 + j) * NA;
                orow[lane]      = ep0 * ipv - en0 * inv;
                orow[lane + 32] = ep1 * ipv - en1 * inv;
            }
        }
    } else {
        // ================= P blocks: 8 users/block =================
        float ru0 = sR[lane], ru1 = sR[lane + 32];
        int row = (blockIdx.x - QB) * 8 + w;
        if (row >= bz) return;
        const float* U = Uemb + (size_t)uidx[row] * D;
        float* us = Ism[w];
        ((float2*)us)[lane] = ((const float2*)U)[lane];
        __syncwarp();

        float acc0 = 0.f, acc1 = 0.f;
#pragma unroll
        for (int d = 0; d < 64; d++) {
            float  u  = us[d];
            float2 a2 = At2[d * 32 + lane];
            acc0 += u * a2.x;
            acc1 += u * a2.y;
        }
        float l0 = acc0 + ru0, l1 = acc1 + ru1;
        float m = fmaxf(l0, l1);
#pragma unroll
        for (int o = 16; o; o >>= 1) m = fmaxf(m, __shfl_xor_sync(0xffffffffu, m, o));
        float e0 = __expf(l0 - m), e1 = __expf(l1 - m);
        float s = e0 + e1;
#pragma unroll
        for (int o = 16; o; o >>= 1) s += __shfl_xor_sync(0xffffffffu, s, o);
        float inv = __fdividef(1.f, s);
        g_P[row * NA + lane]      = e0 * inv;
        g_P[row * NA + lane + 32] = e1 * inv;
    }
}

// ---------------------------------------------------------------------------
// Kernel 2: ratings[b,n] = P[b] . Qd[item[b,n]] + bias[item]; softmax over n.
// One block per b. 8-lane groups gather one 256B row via 2 coalesced LDG.128.
// Unroll x4: all 8 LDG.128 + idx + bias issued before any consume (MLP=8/lane).
// ---------------------------------------------------------------------------
__global__ void __launch_bounds__(256) main_kernel(
        const int* __restrict__ iidx,
        const float* __restrict__ bias,
        float* __restrict__ out, int ns) {
    __shared__ float Ps[64];
    __shared__ float rat[1024];
    __shared__ float red[8];
    int b = blockIdx.x;
    int t = threadIdx.x;
    if (t < 16) ((float4*)Ps)[t] = ((const float4*)(g_P + b * 64))[t];
    __syncthreads();

    int w = t >> 5, lane = t & 31, g = lane >> 3, q = lane & 7;
    float4 p0 = ((float4*)Ps)[q];
    float4 p1 = ((float4*)Ps)[q + 8];
    const int* idxrow = iidx + (size_t)b * ns;
    int nsp = (ns + 127) & ~127;   // padded bound (multiple of 128 samples/iter)

    for (int s0 = w * 16; s0 < nsp; s0 += 128) {
        float4 a[4], c[4];
        float  bv[4];
        int    sarr[4];
        bool   ok[4];
        // -------- batched load phase: no consume until all issued --------
#pragma unroll
        for (int k = 0; k < 4; k++) {
            int s = s0 + k * 4 + g;
            sarr[k] = s;
            ok[k] = (s < ns);
            int item = ok[k] ? idxrow[s] : 0;
            const float4* row = (const float4*)(g_Qd + (size_t)item * 64);
            a[k] = row[q];        // bytes [0,128)
            c[k] = row[q + 8];    // bytes [128,256)
            bv[k] = (ok[k] && q == 0) ? bias[item] : 0.f;
        }
        // -------- compute + reduce phase --------
#pragma unroll
        for (int k = 0; k < 4; k++) {
            float r = a[k].x * p0.x + a[k].y * p0.y + a[k].z * p0.z + a[k].w * p0.w
                    + c[k].x * p1.x + c[k].y * p1.y + c[k].z * p1.z + c[k].w * p1.w;
            r += __shfl_xor_sync(0xffffffffu, r, 1);
            r += __shfl_xor_sync(0xffffffffu, r, 2);
            r += __shfl_xor_sync(0xffffffffu, r, 4);
            if (ok[k] && q == 0) rat[sarr[k]] = r + bv[k];
        }
    }
    __syncthreads();

    // block softmax over rat[0..ns)
    float m = -1e30f;
    for (int s = t; s < ns; s += 256) m = fmaxf(m, rat[s]);
#pragma unroll
    for (int o = 16; o; o >>= 1) m = fmaxf(m, __shfl_xor_sync(0xffffffffu, m, o));
    if (lane == 0) red[w] = m;
    __syncthreads();
    if (t == 0) {
        float v = red[0];
#pragma unroll
        for (int i = 1; i < 8; i++) v = fmaxf(v, red[i]);
        red[0] = v;
    }
    __syncthreads();
    m = red[0];
    __syncthreads();   // protect red[] before sum phase reuses it

    float sum = 0.f;
    for (int s = t; s < ns; s += 256) {
        float e = __expf(rat[s] - m);
        rat[s] = e;
        sum += e;
    }
#pragma unroll
    for (int o = 16; o; o >>= 1) sum += __shfl_xor_sync(0xffffffffu, sum, o);
    if (lane == 0) red[w] = sum;
    __syncthreads();
    if (t == 0) {
        float v = red[0];
#pragma unroll
        for (int i = 1; i < 8; i++) v += red[i];
        red[0] = v;
    }
    __syncthreads();
    float inv = __fdividef(1.f, red[0]);
    float* orow = out + (size_t)b * ns;
    for (int s = t; s < ns; s += 256) orow[s] = rat[s] * inv;
}

// ---------------------------------------------------------------------------
// Launch
// ---------------------------------------------------------------------------
extern "C" void kernel_launch(void* const* d_in, const int* in_sizes, int n_in,
                              void* d_out, int out_size) {
    const int*   uidx = (const int*)d_in[0];
    const int*   iidx = (const int*)d_in[1];
    const float* Uemb = (const float*)d_in[2];
    const float* Iemb = (const float*)d_in[3];
    const float* A    = (const float*)d_in[4];
    const float* Rel  = (const float*)d_in[5];
    const float* bias = (const float*)d_in[6];
    float* out = (float*)d_out;

    int bz    = in_sizes[0];
    int ns    = in_sizes[1] / bz;
    int nitem = in_sizes[3] / D;

    int QB = (nitem + 63) / 64;
    int PB = (bz + 7) / 8;

    prep_kernel<<<QB + PB, 256>>>(uidx, Uemb, Iemb, A, Rel, bz, nitem, QB);
    main_kernel<<<bz, 256>>>(iidx, bias, out, ns);
}

// round 4
// speedup vs baseline: 1.6454x; 1.3606x over previous
#include <cuda_runtime.h>

#define D  64
#define NA 64
#define MAX_ITEM 100000
#define MAX_BZ   1024

// Scratch tables (allocation-free: __device__ globals)
__device__ __align__(16) float g_P[MAX_BZ * NA];            // 256 KB
__device__ __align__(16) float g_Qd[(size_t)MAX_ITEM * NA]; // 25.6 MB, L2-resident

// ---------------------------------------------------------------------------
// Fused prep: blocks [0, QB) compute Qd table (+bias folded); blocks [QB, QB+PB)
// compute P. A staged as padded row-major A_s[a][65]:
//   fill: consecutive threads -> consecutive d -> coalesced global, stride-1 smem.
//   read: lane reads A_s[lane][d] -> bank (lane*65+d)%32 = (lane+d)%32, conflict-free.
// ---------------------------------------------------------------------------
__global__ void __launch_bounds__(256) prep_kernel(
        const int* __restrict__ uidx,
        const float* __restrict__ Uemb,
        const float* __restrict__ Iemb,
        const float* __restrict__ A,
        const float* __restrict__ Rel,
        const float* __restrict__ bias,
        int bz, int nitem, int QB) {
    __shared__ __align__(16) float A_s[64][65];   // 16.6 KB, padded
    __shared__ __align__(16) float sR[128];       // qd: RpA|RnA ; p: RuA
    __shared__ float4 Ism4[8][80];                // native float4: guaranteed 16B align

    int t = threadIdx.x;
    for (int idx = t; idx < 64 * 64; idx += 256)
        A_s[idx >> 6][idx & 63] = A[idx];         // coalesced + conflict-free
    __syncthreads();

    int w = t >> 5, lane = t & 31;
    bool isQ = blockIdx.x < QB;

    // ---- per-block relation projections (A from smem, Rel broadcast) ----
    if (isQ) {
        if (t < 128) {
            int rr = 1 + (t >> 6);       // 1 = Rip, 2 = Rin
            int a  = t & 63;
            const float* rv = Rel + rr * D;
            const float* ar = A_s[a];
            float s = 0.f;
#pragma unroll
            for (int d = 0; d < 64; d++) s += rv[d] * ar[d];
            sR[t] = s;                    // [0,64)=RpA, [64,128)=RnA
        }
    } else {
        if (t < 64) {
            const float* ar = A_s[t];
            float s = 0.f;
#pragma unroll
            for (int d = 0; d < 64; d++) s += Rel[d] * ar[d];
            sR[t] = s;                    // RuA
        }
    }
    __syncthreads();

    if (isQ) {
        // ================= Qd blocks: 64 items/block =================
        float rp0 = sR[lane],      rp1 = sR[lane + 32];
        float rn0 = sR[64 + lane], rn1 = sR[96 + lane];
        const float* Ar0 = A_s[lane];
        const float* Ar1 = A_s[lane + 32];
        int blockBase = blockIdx.x * 64;
#pragma unroll 1
        for (int it = 0; it < 2; it++) {
            int base4 = blockBase + w * 8 + it * 4;   // 4 consecutive items
            if (base4 >= nitem) break;                // nitem % 4 == 0

            // Cooperative load: 4 rows = 256 contiguous floats (16 float4/half-warp).
            const float4* g4 = (const float4*)(Iemb + (size_t)base4 * D);
            float4 v1 = g4[lane];
            float4 v2 = g4[lane + 32];
            __syncwarp();
            {
                // float4 #f covers item j = f>>4 at d = 4q..4q+3 (q = f&15).
                // Interleaved store: slot 5q+k holds d-chunk for item k? No:
                // component j of float4 slot (5q + k) = I[item j][4q + k].
                int f, j, q;
                f = lane;      j = f >> 4; q = f & 15;
#pragma unroll
                for (int k = 0; k < 4; k++)
                    ((float*)&Ism4[w][5 * q + k])[j] = ((float*)&v1)[k];
                f = lane + 32; j = f >> 4; q = f & 15;
#pragma unroll
                for (int k = 0; k < 4; k++)
                    ((float*)&Ism4[w][5 * q + k])[j] = ((float*)&v2)[k];
            }
            __syncwarp();

            float acc00 = 0.f, acc01 = 0.f, acc10 = 0.f, acc11 = 0.f;
            float acc20 = 0.f, acc21 = 0.f, acc30 = 0.f, acc31 = 0.f;
#pragma unroll
            for (int d = 0; d < 64; d++) {
                float a0 = Ar0[d];                    // LDS.32 conflict-free
                float a1 = Ar1[d];                    // LDS.32 conflict-free
                float4 iv = Ism4[w][d + (d >> 2)];    // typed LDS.128 broadcast
                acc00 += iv.x * a0; acc01 += iv.x * a1;
                acc10 += iv.y * a0; acc11 += iv.y * a1;
                acc20 += iv.z * a0; acc21 += iv.z * a1;
                acc30 += iv.w * a0; acc31 += iv.w * a1;
            }

            float L0s[4] = {acc00, acc10, acc20, acc30};
            float L1s[4] = {acc01, acc11, acc21, acc31};
#pragma unroll
            for (int j = 0; j < 4; j++) {
                // shift-free softmax: |logit| <~ 50 << 88 (fp32 exp overflow)
                float ep0 = __expf(L0s[j] + rp0), ep1 = __expf(L1s[j] + rp1);
                float en0 = __expf(L0s[j] + rn0), en1 = __expf(L1s[j] + rn1);
                float sp = ep0 + ep1, sn = en0 + en1;
#pragma unroll
                for (int o = 16; o; o >>= 1) {
                    sp += __shfl_xor_sync(0xffffffffu, sp, o);
                    sn += __shfl_xor_sync(0xffffffffu, sn, o);
                }
                float ipv = __fdividef(1.f, sp);
                float inv = __fdividef(1.f, sn);
                float bb  = bias[base4 + j];          // warp-uniform broadcast
                float* orow = g_Qd + (size_t)(base4 + j) * NA;
                orow[lane]      = ep0 * ipv - en0 * inv + bb;
                orow[lane + 32] = ep1 * ipv - en1 * inv + bb;
            }
        }
    } else {
        // ================= P blocks: 8 users/block =================
        float ru0 = sR[lane], ru1 = sR[lane + 32];
        int row = (blockIdx.x - QB) * 8 + w;
        if (row >= bz) return;
        const float* U = Uemb + (size_t)uidx[row] * D;
        float* us = (float*)Ism4[w];
        ((float2*)us)[lane] = ((const float2*)U)[lane];
        __syncwarp();

        const float* Ar0 = A_s[lane];
        const float* Ar1 = A_s[lane + 32];
        float acc0 = 0.f, acc1 = 0.f;
#pragma unroll
        for (int d = 0; d < 64; d++) {
            float u = us[d];
            acc0 += u * Ar0[d];
            acc1 += u * Ar1[d];
        }
        float l0 = acc0 + ru0, l1 = acc1 + ru1;
        float m = fmaxf(l0, l1);
#pragma unroll
        for (int o = 16; o; o >>= 1) m = fmaxf(m, __shfl_xor_sync(0xffffffffu, m, o));
        float e0 = __expf(l0 - m), e1 = __expf(l1 - m);
        float s = e0 + e1;
#pragma unroll
        for (int o = 16; o; o >>= 1) s += __shfl_xor_sync(0xffffffffu, s, o);
        float inv = __fdividef(1.f, s);
        g_P[row * NA + lane]      = e0 * inv;
        g_P[row * NA + lane + 32] = e1 * inv;
    }
}

// ---------------------------------------------------------------------------
// Main: ratings[b,n] = P[b] . Qd'[item[b,n]]  (bias pre-folded); softmax over n.
// One block per b. 8-lane groups gather one 256B row via 2 coalesced LDG.128.
// Batched x4: all loads issued before any consume (MLP=8/lane).
// ---------------------------------------------------------------------------
__global__ void __launch_bounds__(256) main_kernel(
        const int* __restrict__ iidx,
        float* __restrict__ out, int ns) {
    __shared__ __align__(16) float Ps[64];
    __shared__ __align__(16) float rat[1024];
    __shared__ float red[8];
    int b = blockIdx.x;
    int t = threadIdx.x;
    if (t < 16) ((float4*)Ps)[t] = ((const float4*)(g_P + b * 64))[t];
    __syncthreads();

    int w = t >> 5, lane = t & 31, g = lane >> 3, q = lane & 7;
    float4 p0 = ((float4*)Ps)[q];
    float4 p1 = ((float4*)Ps)[q + 8];
    const int* idxrow = iidx + (size_t)b * ns;
    int nsp = (ns + 127) & ~127;   // padded bound (128 samples/iter)

    for (int s0 = w * 16; s0 < nsp; s0 += 128) {
        float4 a[4], c[4];
        // -------- batched load phase: no consume until all issued --------
#pragma unroll
        for (int k = 0; k < 4; k++) {
            int s = s0 + k * 4 + g;
            int item = (s < ns) ? idxrow[s] : 0;
            const float4* row = (const float4*)(g_Qd + (size_t)item * 64);
            a[k] = row[q];        // bytes [0,128)
            c[k] = row[q + 8];    // bytes [128,256)
        }
        // -------- compute + reduce phase --------
#pragma unroll
        for (int k = 0; k < 4; k++) {
            float r = a[k].x * p0.x + a[k].y * p0.y + a[k].z * p0.z + a[k].w * p0.w
                    + c[k].x * p1.x + c[k].y * p1.y + c[k].z * p1.z + c[k].w * p1.w;
            r += __shfl_xor_sync(0xffffffffu, r, 1);
            r += __shfl_xor_sync(0xffffffffu, r, 2);
            r += __shfl_xor_sync(0xffffffffu, r, 4);
            int s = s0 + k * 4 + g;
            if (s < ns && q == 0) rat[s] = r;
        }
    }
    __syncthreads();

    // block softmax over rat[0..ns)
    float m = -1e30f;
    for (int s = t; s < ns; s += 256) m = fmaxf(m, rat[s]);
#pragma unroll
    for (int o = 16; o; o >>= 1) m = fmaxf(m, __shfl_xor_sync(0xffffffffu, m, o));
    if (lane == 0) red[w] = m;
    __syncthreads();
    if (t == 0) {
        float v = red[0];
#pragma unroll
        for (int i = 1; i < 8; i++) v = fmaxf(v, red[i]);
        red[0] = v;
    }
    __syncthreads();
    m = red[0];
    __syncthreads();   // protect red[] before sum phase reuses it

    float sum = 0.f;
    for (int s = t; s < ns; s += 256) {
        float e = __expf(rat[s] - m);
        rat[s] = e;
        sum += e;
    }
#pragma unroll
    for (int o = 16; o; o >>= 1) sum += __shfl_xor_sync(0xffffffffu, sum, o);
    if (lane == 0) red[w] = sum;
    __syncthreads();
    if (t == 0) {
        float v = red[0];
#pragma unroll
        for (int i = 1; i < 8; i++) v += red[i];
        red[0] = v;
    }
    __syncthreads();
    float inv = __fdividef(1.f, red[0]);
    float* orow = out + (size_t)b * ns;
    for (int s = t; s < ns; s += 256) orow[s] = rat[s] * inv;
}

// ---------------------------------------------------------------------------
// Launch
// ---------------------------------------------------------------------------
extern "C" void kernel_launch(void* const* d_in, const int* in_sizes, int n_in,
                              void* d_out, int out_size) {
    const int*   uidx = (const int*)d_in[0];
    const int*   iidx = (const int*)d_in[1];
    const float* Uemb = (const float*)d_in[2];
    const float* Iemb = (const float*)d_in[3];
    const float* A    = (const float*)d_in[4];
    const float* Rel  = (const float*)d_in[5];
    const float* bias = (const float*)d_in[6];
    float* out = (float*)d_out;

    int bz    = in_sizes[0];
    int ns    = in_sizes[1] / bz;
    int nitem = in_sizes[3] / D;

    int QB = (nitem + 63) / 64;
    int PB = (bz + 7) / 8;

    prep_kernel<<<QB + PB, 256>>>(uidx, Uemb, Iemb, A, Rel, bias, bz, nitem, QB);
    main_kernel<<<bz, 256>>>(iidx, out, ns);
}